// round 2
// baseline (speedup 1.0000x reference)
#include <cuda_runtime.h>
#include <math.h>

// ---------------- problem constants ----------------
#define B_EVT   100000
#define N_NODES 500000
#define MEM_D   500
#define MSG_D   100
#define TIME_D  100
#define EDGE_F  101
#define RAW_D   701          // MEM_D + EDGE_F + TIME_D
#define RAW_P   704          // padded row stride for g_raw
#define HID_D   350
#define HID_P   352          // padded row stride for g_act
#define KX      600          // stacked K for GRU GEMM (h:500 | msg:100)
#define G3      1500         // 3*MEM_D gate width

// ---------------- static scratch (no allocs allowed) ----------------
__device__ int   g_winner[N_NODES];
__device__ float g_raw[(size_t)B_EVT * RAW_P];   // [h | edge_feats->msg | tenc | pad]
__device__ float g_act[(size_t)B_EVT * HID_P];   // relu(raw@W1+b1)
__device__ float g_wstack[KX * G3];              // [W_hh ; W_ih]

__device__ __forceinline__ float sigmoidf_(float x) { return 1.f / (1.f + expf(-x)); }

// ---------------- winner detection: last event index per node ----------------
__global__ void k_winner(const int* __restrict__ node_ids) {
    int e = blockIdx.x * blockDim.x + threadIdx.x;
    if (e < B_EVT) atomicMax(&g_winner[node_ids[e]], e);
}

// ---------------- stack W_hh (rows 0..499) and W_ih (rows 500..599) ----------------
__global__ void k_wstack(const float* __restrict__ W_ih, const float* __restrict__ W_hh) {
    int i = blockIdx.x * blockDim.x + threadIdx.x;
    if (i >= KX * G3) return;
    int k = i / G3, j = i - k * G3;
    g_wstack[i] = (k < MEM_D) ? W_hh[k * G3 + j] : W_ih[(k - MEM_D) * G3 + j];
}

// ---------------- build raw = [memory[n] | edge_feats | cos(dt*w+b) | 0pad] ----------------
// CRITICAL: the cos argument is O(1e6); 1 ULP there is ~0.06. The reference (XLA)
// computes mul and add as SEPARATE roundings (no FMA contraction). We must match
// that exactly: __fmul_rn then __fadd_rn, then accurate cosf (libdevice __nv_cosf,
// same function XLA lowers to).
__global__ void k_raw(const float* __restrict__ memory,
                      const float* __restrict__ last_update,
                      const float* __restrict__ edge_feats,
                      const float* __restrict__ w_t,
                      const float* __restrict__ b_t,
                      const int*   __restrict__ node_ids,
                      const int*   __restrict__ edge_times) {
    int e = blockIdx.x;
    int n = node_ids[e];
    float tf = (float)edge_times[e];
    float dt = __fadd_rn(tf, -last_update[n]);
    const float* mrow = memory + (size_t)n * MEM_D;
    float* dst = g_raw + (size_t)e * RAW_P;
    for (int i = threadIdx.x; i < RAW_P; i += blockDim.x) {
        float v;
        if (i < MEM_D)                 v = mrow[i];
        else if (i < MEM_D + EDGE_F)   v = edge_feats[(size_t)e * EDGE_F + (i - MEM_D)];
        else if (i < RAW_D) {
            int t = i - (MEM_D + EDGE_F);
            float prod = __fmul_rn(dt, w_t[t]);      // separate rounding (no FMA)
            float arg  = __fadd_rn(prod, b_t[t]);    // separate rounding (no FMA)
            v = cosf(arg);
        } else                         v = 0.f;
        dst[i] = v;
    }
}

// ---------------- generic tiled SGEMM: C = act(A[MxK] @ W[KxN] + bias) ----------------
// BM=128, BN=64, BK=16, 256 threads, 8x4 micro-tile per thread.
template<int RELU>
__global__ __launch_bounds__(256)
void k_gemm(const float* __restrict__ A, int lda,
            const float* __restrict__ W, int ldw,
            const float* __restrict__ bias,
            float* __restrict__ C, int ldc,
            int M, int N, int K) {
    const int BM = 128, BN = 64, BK = 16;
    __shared__ float As[BK][BM + 1];
    __shared__ float Ws[BK][BN];
    int tid = threadIdx.x;
    int tx = tid & 15, ty = tid >> 4;
    int m0 = blockIdx.x * BM, n0 = blockIdx.y * BN;

    float acc[8][4];
#pragma unroll
    for (int i = 0; i < 8; i++)
#pragma unroll
        for (int j = 0; j < 4; j++) acc[i][j] = 0.f;

    for (int k0 = 0; k0 < K; k0 += BK) {
#pragma unroll
        for (int i = tid; i < BM * BK; i += 256) {
            int m = i >> 4, k = i & 15;
            int gm = m0 + m, gk = k0 + k;
            As[k][m] = (gm < M && gk < K) ? A[(size_t)gm * lda + gk] : 0.f;
        }
#pragma unroll
        for (int i = tid; i < BK * BN; i += 256) {
            int k = i >> 6, n = i & 63;
            int gk = k0 + k, gn = n0 + n;
            Ws[k][n] = (gk < K && gn < N) ? W[(size_t)gk * ldw + gn] : 0.f;
        }
        __syncthreads();
#pragma unroll
        for (int k = 0; k < BK; k++) {
            float a[8], b[4];
#pragma unroll
            for (int i = 0; i < 8; i++) a[i] = As[k][ty * 8 + i];
#pragma unroll
            for (int j = 0; j < 4; j++) b[j] = Ws[k][tx * 4 + j];
#pragma unroll
            for (int i = 0; i < 8; i++)
#pragma unroll
                for (int j = 0; j < 4; j++) acc[i][j] += a[i] * b[j];
        }
        __syncthreads();
    }
#pragma unroll
    for (int i = 0; i < 8; i++) {
        int m = m0 + ty * 8 + i;
        if (m >= M) continue;
#pragma unroll
        for (int j = 0; j < 4; j++) {
            int n = n0 + tx * 4 + j;
            if (n >= N) continue;
            float v = acc[i][j] + bias[n];
            if (RELU) v = fmaxf(v, 0.f);
            C[(size_t)m * ldc + n] = v;
        }
    }
}

// ---------------- fused GRU GEMM ----------------
// X = g_raw[:, 0:600] = [h | msg]. For output col j in [0,500):
//   s_r  = sum_k X[k]*Wstk[k][j]       (K=600)
//   s_z  = sum_k X[k]*Wstk[k][500+j]   (K=600)
//   gh_n = sum_{k<500}  X*Wstk[k][1000+j],  gi_n = sum_{k>=500} X*Wstk[k][1000+j]
//   h_new = (1-z)*tanh(gi_n+b_ih_n + r*(gh_n+b_hh_n)) + z*h
// BM=128, BN=32, BK=20 (divides both 600 and 500), 256 threads, 8x2 micro-tile.
__global__ __launch_bounds__(256)
void k_gru(const float* __restrict__ b_ih,
           const float* __restrict__ b_hh,
           float* __restrict__ out) {
    const int BM = 128, BN = 32, BK = 20;
    __shared__ float Xs[BK][BM + 1];
    __shared__ float Wr[BK][BN], Wz[BK][BN], Wn[BK][BN];
    int tid = threadIdx.x;
    int tx = tid & 15, ty = tid >> 4;
    int m0 = blockIdx.x * BM, n0 = blockIdx.y * BN;

    float ar[8][2], az[8][2], ani[8][2], anh[8][2];
#pragma unroll
    for (int i = 0; i < 8; i++)
#pragma unroll
        for (int j = 0; j < 2; j++) { ar[i][j] = az[i][j] = ani[i][j] = anh[i][j] = 0.f; }

    for (int kc = 0; kc < KX / BK; kc++) {
        int k0 = kc * BK;
        for (int i = tid; i < BM * BK; i += 256) {
            int m = i / BK, k = i - m * BK;
            int gm = m0 + m;
            Xs[k][m] = (gm < B_EVT) ? g_raw[(size_t)gm * RAW_P + k0 + k] : 0.f;
        }
        for (int i = tid; i < 3 * BK * BN; i += 256) {
            int t = i / (BK * BN), r = i - t * (BK * BN);
            int k = r / BN, n = r - k * BN;
            int gn = n0 + n;
            float v = (gn < MEM_D) ? g_wstack[(size_t)(k0 + k) * G3 + t * MEM_D + gn] : 0.f;
            if (t == 0) Wr[k][n] = v;
            else if (t == 1) Wz[k][n] = v;
            else Wn[k][n] = v;
        }
        __syncthreads();
        bool isH = (k0 < MEM_D);   // whole chunk on one side of 500 (500 % 20 == 0)
#pragma unroll
        for (int k = 0; k < BK; k++) {
            float a[8], br[2], bz[2], bn[2];
#pragma unroll
            for (int i = 0; i < 8; i++) a[i] = Xs[k][ty * 8 + i];
#pragma unroll
            for (int j = 0; j < 2; j++) {
                br[j] = Wr[k][tx * 2 + j];
                bz[j] = Wz[k][tx * 2 + j];
                bn[j] = Wn[k][tx * 2 + j];
            }
#pragma unroll
            for (int i = 0; i < 8; i++)
#pragma unroll
                for (int j = 0; j < 2; j++) {
                    ar[i][j] += a[i] * br[j];
                    az[i][j] += a[i] * bz[j];
                    if (isH) anh[i][j] += a[i] * bn[j];
                    else     ani[i][j] += a[i] * bn[j];
                }
        }
        __syncthreads();
    }

#pragma unroll
    for (int i = 0; i < 8; i++) {
        int m = m0 + ty * 8 + i;
        if (m >= B_EVT) continue;
#pragma unroll
        for (int j = 0; j < 2; j++) {
            int n = n0 + tx * 2 + j;
            if (n >= MEM_D) continue;
            float r  = sigmoidf_(ar[i][j] + b_ih[n] + b_hh[n]);
            float z  = sigmoidf_(az[i][j] + b_ih[MEM_D + n] + b_hh[MEM_D + n]);
            float nn = tanhf(ani[i][j] + b_ih[2 * MEM_D + n] +
                             r * (anh[i][j] + b_hh[2 * MEM_D + n]));
            float h  = g_raw[(size_t)m * RAW_P + n];
            out[(size_t)m * MEM_D + n] = (1.f - z) * nn + z * h;
        }
    }
}

// ---------------- non-winner rows copy the winner's h_new ----------------
__global__ void k_fixup(const int* __restrict__ node_ids, float* __restrict__ out) {
    int e = blockIdx.x;
    int w = g_winner[node_ids[e]];
    if (w == e) return;
    const float4* src = (const float4*)(out + (size_t)w * MEM_D);
    float4*       dst = (float4*)(out + (size_t)e * MEM_D);
    for (int i = threadIdx.x; i < MEM_D / 4; i += blockDim.x) dst[i] = src[i];
}

// ---------------- launch ----------------
extern "C" void kernel_launch(void* const* d_in, const int* in_sizes, int n_in,
                              void* d_out, int out_size) {
    const float* memory      = (const float*)d_in[0];
    const float* last_update = (const float*)d_in[1];
    const float* edge_feats  = (const float*)d_in[2];
    const float* w_t         = (const float*)d_in[3];
    const float* b_t         = (const float*)d_in[4];
    const float* W1          = (const float*)d_in[5];
    const float* b1          = (const float*)d_in[6];
    const float* W2          = (const float*)d_in[7];
    const float* b2          = (const float*)d_in[8];
    const float* W_ih        = (const float*)d_in[9];
    const float* W_hh        = (const float*)d_in[10];
    const float* b_ih        = (const float*)d_in[11];
    const float* b_hh        = (const float*)d_in[12];
    // d_in[13] default_memory: provably unused (all output nodes are touched, times>=1)
    const int*   node_ids    = (const int*)d_in[14];
    const int*   edge_times  = (const int*)d_in[15];
    float* out = (float*)d_out;

    void *winner_p, *raw_p, *act_p;
    cudaGetSymbolAddress(&winner_p, g_winner);
    cudaGetSymbolAddress(&raw_p,    g_raw);
    cudaGetSymbolAddress(&act_p,    g_act);
    float* raw = (float*)raw_p;
    float* act = (float*)act_p;

    cudaMemsetAsync(winner_p, 0xFF, sizeof(int) * N_NODES);
    k_winner<<<(B_EVT + 255) / 256, 256>>>(node_ids);
    k_wstack<<<(KX * G3 + 255) / 256, 256>>>(W_ih, W_hh);
    k_raw<<<B_EVT, 128>>>(memory, last_update, edge_feats, w_t, b_t, node_ids, edge_times);

    // MLP layer 1: act = relu(raw @ W1 + b1)
    {
        dim3 g((B_EVT + 127) / 128, (HID_D + 63) / 64);
        k_gemm<1><<<g, 256>>>(raw, RAW_P, W1, HID_D, b1, act, HID_P, B_EVT, HID_D, RAW_D);
    }
    // MLP layer 2: msg -> written into g_raw cols [500,600) (edge_feats region is dead now)
    {
        dim3 g((B_EVT + 127) / 128, (MSG_D + 63) / 64);
        k_gemm<0><<<g, 256>>>(act, HID_P, W2, MSG_D, b2, raw + MEM_D, RAW_P, B_EVT, MSG_D, HID_D);
    }
    // Fused GRU: out[e] = h_new[e] for every event
    {
        dim3 g((B_EVT + 127) / 128, (MEM_D + 31) / 32);
        k_gru<<<g, 256>>>(b_ih, b_hh, out);
    }
    // Replace non-winner rows with their node's winner row
    k_fixup<<<B_EVT, 128>>>(node_ids, out);
}

// round 4
// speedup vs baseline: 1.2932x; 1.2932x over previous
#include <cuda_runtime.h>
#include <math.h>
#include <stdint.h>

// ---------------- problem constants ----------------
#define B_EVT   100000
#define N_NODES 500000
#define MEM_D   500
#define MSG_D   100
#define TIME_D  100
#define EDGE_F  101
#define RAW_D   701
#define RAW_P   704          // padded row stride for g_raw (%32==0)
#define HID_D   350
#define HID_P   352          // padded row stride for g_act (%32==0)
#define G3      1500         // 3*MEM_D
#define KGRU    608          // [msg(100)|pad4|h(500)|pad4]
#define KB      104          // boundary msg|h  (multiple of 8)

// ---------------- static scratch ----------------
__device__ __align__(16) int   g_winner[N_NODES];
__device__ __align__(16) float g_raw[(size_t)B_EVT * RAW_P];   // [h | edge->msg | tenc | 0]
__device__ __align__(16) float g_act[(size_t)B_EVT * HID_P];
__device__ __align__(16) float g_wstk[(size_t)KGRU * G3];      // rows: ih(100),0(4),hh(500),0(4)

__device__ __forceinline__ float sigmoidf_(float x) { return 1.f / (1.f + expf(-x)); }

__device__ __forceinline__ uint32_t f2tf32(float x) {
    uint32_t r; asm("cvt.rna.tf32.f32 %0, %1;" : "=r"(r) : "f"(x)); return r;
}

__device__ __forceinline__ void mma8(float c[4], const uint32_t a[4], const uint32_t b[2]) {
    asm volatile(
        "mma.sync.aligned.m16n8k8.row.col.f32.tf32.tf32.f32 "
        "{%0,%1,%2,%3},{%4,%5,%6,%7},{%8,%9},{%0,%1,%2,%3};"
        : "+f"(c[0]), "+f"(c[1]), "+f"(c[2]), "+f"(c[3])
        : "r"(a[0]), "r"(a[1]), "r"(a[2]), "r"(a[3]), "r"(b[0]), "r"(b[1]));
}

// ---------------- winner: last event index per node ----------------
__global__ void k_winner(const int* __restrict__ node_ids) {
    int e = blockIdx.x * blockDim.x + threadIdx.x;
    if (e < B_EVT) atomicMax(&g_winner[node_ids[e]], e);
}

// ---------------- build padded stacked weight [ih;0;hh;0] ----------------
__global__ void k_wstack(const float* __restrict__ W_ih, const float* __restrict__ W_hh) {
    int i = blockIdx.x * blockDim.x + threadIdx.x;
    if (i >= KGRU * G3) return;
    int k = i / G3, j = i - k * G3;
    float v = 0.f;
    if (k < MSG_D)                 v = W_ih[k * G3 + j];
    else if (k >= KB && k < KB + MEM_D) v = W_hh[(k - KB) * G3 + j];
    g_wstk[i] = v;
}

// ---------------- raw = [memory[n] | edge_feats | cos(dt*w+b) | 0] ----------------
// cos argument is O(1e6): must round mul and add SEPARATELY (XLA has no FMA
// contraction there), then accurate cosf.
__global__ void k_raw(const float* __restrict__ memory,
                      const float* __restrict__ last_update,
                      const float* __restrict__ edge_feats,
                      const float* __restrict__ w_t,
                      const float* __restrict__ b_t,
                      const int*   __restrict__ node_ids,
                      const int*   __restrict__ edge_times) {
    int e = blockIdx.x;
    int n = node_ids[e];
    float dt = __fadd_rn((float)edge_times[e], -last_update[n]);
    const float* mrow = memory + (size_t)n * MEM_D;
    float* dst = g_raw + (size_t)e * RAW_P;
    for (int i = threadIdx.x; i < RAW_P; i += blockDim.x) {
        float v;
        if (i < MEM_D)                 v = mrow[i];
        else if (i < MEM_D + EDGE_F)   v = edge_feats[(size_t)e * EDGE_F + (i - MEM_D)];
        else if (i < RAW_D) {
            int t = i - (MEM_D + EDGE_F);
            float arg = __fadd_rn(__fmul_rn(dt, w_t[t]), b_t[t]);
            v = cosf(arg);
        } else                         v = 0.f;
        dst[i] = v;
    }
}

// ---------------- TF32 mma GEMM: C = act(A@W + bias) ----------------
// BM=128, BN=64, BK=32. 8 warps: warp grid 2m x 4n, warp tile 64x16.
// Kpad % 32 == 0; A must be zero in padded cols [Kw,Kpad). W/bias bounded by Kw/Nw;
// store bounded by Nc (Nc>=Nw pads C with act(0+0)).
template<int RELU>
__global__ __launch_bounds__(256)
void k_gemm_t(const float* __restrict__ A, int lda,
              const float* __restrict__ W, int ldw, int Kw,
              const float* __restrict__ bias,
              float* __restrict__ C, int ldc,
              int M, int Nw, int Nc, int Kpad) {
    __shared__ uint32_t As[32][136];
    __shared__ uint32_t Ws[32][72];
    const int tid = threadIdx.x;
    const int lane = tid & 31, wid = tid >> 5;
    const int gid = lane >> 2, tig = lane & 3;
    const int wm = wid & 1, wn = wid >> 1;          // 2 x 4 warps
    const int m0 = blockIdx.x * 128, n0 = blockIdx.y * 64;

    float acc[4][2][4];
#pragma unroll
    for (int i = 0; i < 4; i++)
#pragma unroll
        for (int j = 0; j < 2; j++)
#pragma unroll
            for (int c = 0; c < 4; c++) acc[i][j][c] = 0.f;

    for (int k0 = 0; k0 < Kpad; k0 += 32) {
        // A tile: 128x32, float4 global loads
#pragma unroll
        for (int it = 0; it < 4; it++) {
            int r = (tid >> 3) + it * 32;
            int c4 = (tid & 7) * 4;
            int gm = m0 + r;
            float4 v = make_float4(0.f, 0.f, 0.f, 0.f);
            if (gm < M) v = *(const float4*)(A + (size_t)gm * lda + k0 + c4);
            As[c4 + 0][r] = f2tf32(v.x);
            As[c4 + 1][r] = f2tf32(v.y);
            As[c4 + 2][r] = f2tf32(v.z);
            As[c4 + 3][r] = f2tf32(v.w);
        }
        // W tile: 32x64 scalar (ldw not 16B aligned in general)
#pragma unroll
        for (int it = 0; it < 8; it++) {
            int idx = tid + it * 256;
            int k = idx >> 6, n = idx & 63;
            int gk = k0 + k, gn = n0 + n;
            float v = (gk < Kw && gn < Nw) ? W[(size_t)gk * ldw + gn] : 0.f;
            Ws[k][n] = f2tf32(v);
        }
        __syncthreads();
#pragma unroll
        for (int s = 0; s < 4; s++) {
            int kb = s * 8;
            uint32_t a[4][4], b[2][2];
#pragma unroll
            for (int mf = 0; mf < 4; mf++) {
                int r0 = wm * 64 + mf * 16 + gid;
                a[mf][0] = As[kb + tig][r0];
                a[mf][1] = As[kb + tig][r0 + 8];
                a[mf][2] = As[kb + tig + 4][r0];
                a[mf][3] = As[kb + tig + 4][r0 + 8];
            }
#pragma unroll
            for (int nf = 0; nf < 2; nf++) {
                int c0 = wn * 16 + nf * 8 + gid;
                b[nf][0] = Ws[kb + tig][c0];
                b[nf][1] = Ws[kb + tig + 4][c0];
            }
#pragma unroll
            for (int mf = 0; mf < 4; mf++)
#pragma unroll
                for (int nf = 0; nf < 2; nf++) mma8(acc[mf][nf], a[mf], b[nf]);
        }
        __syncthreads();
    }
#pragma unroll
    for (int mf = 0; mf < 4; mf++)
#pragma unroll
        for (int nf = 0; nf < 2; nf++)
#pragma unroll
            for (int c = 0; c < 4; c++) {
                int row = m0 + wm * 64 + mf * 16 + gid + ((c & 2) ? 8 : 0);
                int col = n0 + wn * 16 + nf * 8 + tig * 2 + (c & 1);
                if (row < M && col < Nc) {
                    float bv = (col < Nw) ? bias[col] : 0.f;
                    float v = acc[mf][nf][c] + bv;
                    if (RELU) v = fmaxf(v, 0.f);
                    C[(size_t)row * ldc + col] = v;
                }
            }
}

// ---------------- fused TF32 GRU ----------------
// X[m,k]: k<104 -> msg (raw col 500+k, 0 for k>=100); k>=104 -> h (raw col k-104).
// Per output col n: r = sig(Sr+b), z = sig(Sz+b), nn = tanh(Si + b_ih_n + r*(Sh + b_hh_n))
// where Wn accumulation splits by k<104 (Si) vs k>=104 (Sh).
// BM=128, BN=32, BK=32; 8 warps: 4m x 2n grid, warp tile 32x16.
__global__ __launch_bounds__(256, 2)
void k_gru_t(const float* __restrict__ b_ih,
             const float* __restrict__ b_hh,
             float* __restrict__ out) {
    __shared__ uint32_t Xs[32][136];
    __shared__ uint32_t Wg[3][32][40];
    const int tid = threadIdx.x;
    const int lane = tid & 31, wid = tid >> 5;
    const int gid = lane >> 2, tig = lane & 3;
    const int wm = wid >> 1, wn = wid & 1;          // 4 x 2 warps
    const int m0 = blockIdx.x * 128, n0 = blockIdx.y * 32;

    float ar[2][2][4], az[2][2][4], ani[2][2][4], anh[2][2][4];
#pragma unroll
    for (int i = 0; i < 2; i++)
#pragma unroll
        for (int j = 0; j < 2; j++)
#pragma unroll
            for (int c = 0; c < 4; c++) {
                ar[i][j][c] = az[i][j][c] = ani[i][j][c] = anh[i][j][c] = 0.f;
            }

    for (int k0 = 0; k0 < KGRU; k0 += 32) {
        // X tile (with column remap), 128x32
#pragma unroll
        for (int it = 0; it < 16; it++) {
            int idx = tid + it * 256;
            int m = idx >> 5, kk = idx & 31;
            int gm = m0 + m, gk = k0 + kk;
            float v = 0.f;
            if (gm < B_EVT) {
                if (gk < KB) { if (gk < MSG_D) v = g_raw[(size_t)gm * RAW_P + MEM_D + gk]; }
                else         v = g_raw[(size_t)gm * RAW_P + (gk - KB)];
            }
            Xs[kk][m] = f2tf32(v);
        }
        // 3 gate weight slabs, each 32x32
#pragma unroll
        for (int it = 0; it < 12; it++) {
            int idx = tid + it * 256;
            int g = idx >> 10, rem = idx & 1023;
            int k = rem >> 5, n = rem & 31;
            int gn = n0 + n;
            float v = (gn < MEM_D) ? g_wstk[(size_t)(k0 + k) * G3 + g * MEM_D + gn] : 0.f;
            Wg[g][k][n] = f2tf32(v);
        }
        __syncthreads();
#pragma unroll
        for (int s = 0; s < 4; s++) {
            int kb = s * 8;
            bool ihSide = (k0 + kb) < KB;
            uint32_t a[2][4], br[2][2], bz[2][2], bn[2][2];
#pragma unroll
            for (int mf = 0; mf < 2; mf++) {
                int r0 = wm * 32 + mf * 16 + gid;
                a[mf][0] = Xs[kb + tig][r0];
                a[mf][1] = Xs[kb + tig][r0 + 8];
                a[mf][2] = Xs[kb + tig + 4][r0];
                a[mf][3] = Xs[kb + tig + 4][r0 + 8];
            }
#pragma unroll
            for (int nf = 0; nf < 2; nf++) {
                int c0 = wn * 16 + nf * 8 + gid;
                br[nf][0] = Wg[0][kb + tig][c0];     br[nf][1] = Wg[0][kb + tig + 4][c0];
                bz[nf][0] = Wg[1][kb + tig][c0];     bz[nf][1] = Wg[1][kb + tig + 4][c0];
                bn[nf][0] = Wg[2][kb + tig][c0];     bn[nf][1] = Wg[2][kb + tig + 4][c0];
            }
#pragma unroll
            for (int mf = 0; mf < 2; mf++)
#pragma unroll
                for (int nf = 0; nf < 2; nf++) {
                    mma8(ar[mf][nf], a[mf], br[nf]);
                    mma8(az[mf][nf], a[mf], bz[nf]);
                    if (ihSide) mma8(ani[mf][nf], a[mf], bn[nf]);
                    else        mma8(anh[mf][nf], a[mf], bn[nf]);
                }
        }
        __syncthreads();
    }

#pragma unroll
    for (int mf = 0; mf < 2; mf++)
#pragma unroll
        for (int nf = 0; nf < 2; nf++)
#pragma unroll
            for (int c = 0; c < 4; c++) {
                int rm = m0 + wm * 32 + mf * 16 + gid + ((c & 2) ? 8 : 0);
                int cn = n0 + wn * 16 + nf * 8 + tig * 2 + (c & 1);
                if (rm < B_EVT && cn < MEM_D) {
                    float r  = sigmoidf_(ar[mf][nf][c] + b_ih[cn] + b_hh[cn]);
                    float z  = sigmoidf_(az[mf][nf][c] + b_ih[MEM_D + cn] + b_hh[MEM_D + cn]);
                    float nn = tanhf(ani[mf][nf][c] + b_ih[2 * MEM_D + cn] +
                                     r * (anh[mf][nf][c] + b_hh[2 * MEM_D + cn]));
                    float h  = g_raw[(size_t)rm * RAW_P + cn];
                    out[(size_t)rm * MEM_D + cn] = (1.f - z) * nn + z * h;
                }
            }
}

// ---------------- non-winner rows copy the winner's row ----------------
__global__ void k_fixup(const int* __restrict__ node_ids, float* __restrict__ out) {
    int e = blockIdx.x;
    int w = g_winner[node_ids[e]];
    if (w == e) return;
    const float4* src = (const float4*)(out + (size_t)w * MEM_D);
    float4*       dst = (float4*)(out + (size_t)e * MEM_D);
    for (int i = threadIdx.x; i < MEM_D / 4; i += blockDim.x) dst[i] = src[i];
}

// ---------------- launch ----------------
extern "C" void kernel_launch(void* const* d_in, const int* in_sizes, int n_in,
                              void* d_out, int out_size) {
    const float* memory      = (const float*)d_in[0];
    const float* last_update = (const float*)d_in[1];
    const float* edge_feats  = (const float*)d_in[2];
    const float* w_t         = (const float*)d_in[3];
    const float* b_t         = (const float*)d_in[4];
    const float* W1          = (const float*)d_in[5];
    const float* b1          = (const float*)d_in[6];
    const float* W2          = (const float*)d_in[7];
    const float* b2          = (const float*)d_in[8];
    const float* W_ih        = (const float*)d_in[9];
    const float* W_hh        = (const float*)d_in[10];
    const float* b_ih        = (const float*)d_in[11];
    const float* b_hh        = (const float*)d_in[12];
    // d_in[13] default_memory: dead (every output node is touched, times >= 1)
    const int*   node_ids    = (const int*)d_in[14];
    const int*   edge_times  = (const int*)d_in[15];
    float* out = (float*)d_out;

    void *winner_p, *raw_p, *act_p;
    cudaGetSymbolAddress(&winner_p, g_winner);
    cudaGetSymbolAddress(&raw_p,    g_raw);
    cudaGetSymbolAddress(&act_p,    g_act);
    float* raw = (float*)raw_p;
    float* act = (float*)act_p;

    cudaMemsetAsync(winner_p, 0xFF, sizeof(int) * N_NODES);
    k_winner<<<(B_EVT + 255) / 256, 256>>>(node_ids);
    k_wstack<<<(KGRU * G3 + 255) / 256, 256>>>(W_ih, W_hh);
    k_raw<<<B_EVT, 128>>>(memory, last_update, edge_feats, w_t, b_t, node_ids, edge_times);

    // MLP1: act[:, :352] = relu(raw @ W1 + b1), pad cols written as 0
    {
        dim3 g((B_EVT + 127) / 128, (HID_P + 63) / 64);
        k_gemm_t<1><<<g, 256>>>(raw, RAW_P, W1, HID_D, RAW_D, b1,
                                act, HID_P, B_EVT, HID_D, HID_P, RAW_P);
    }
    // MLP2: msg -> raw cols [500,600)
    {
        dim3 g((B_EVT + 127) / 128, (MSG_D + 63) / 64);
        k_gemm_t<0><<<g, 256>>>(act, HID_P, W2, MSG_D, HID_D, b2,
                                raw + MEM_D, RAW_P, B_EVT, MSG_D, MSG_D, HID_P);
    }
    // Fused GRU -> out (all events)
    {
        dim3 g((B_EVT + 127) / 128, (MEM_D + 31) / 32);
        k_gru_t<<<g, 256>>>(b_ih, b_hh, out);
    }
    k_fixup<<<B_EVT, 128>>>(node_ids, out);
}

// round 6
// speedup vs baseline: 5.4015x; 4.1769x over previous
#include <cuda_runtime.h>
#include <math.h>
#include <stdint.h>

// ---------------- problem constants ----------------
#define B_EVT   100000
#define N_NODES 500000
#define MEM_D   500
#define MSG_D   100
#define TIME_D  100
#define EDGE_F  101
#define RAW_D   701
#define RAW_P   704          // tf32 raw row stride
#define ACT_P   352          // tf32 act row stride
#define KGRU    608          // [msg(100)|pad4|h(500)|pad4]
#define KB      104          // msg|h boundary (mult of 8)
#define H_P     512          // fp32 h row stride
#define W1_P    384          // w1t col pitch (>= 352 + 32 edge)
#define W2_P    128
#define SLAB    512          // wstk per-gate col pitch
#define WSTK_P  1536         // 3*SLAB
#define MBLK    782          // ceil(100000/128)

// ---------------- static scratch ----------------
__device__ __align__(16) int      g_winner[N_NODES];
__device__ __align__(16) uint32_t g_rawt[(size_t)B_EVT * RAW_P];  // tf32 [h|edge|tenc|0]
__device__ __align__(16) uint32_t g_act [(size_t)B_EVT * ACT_P];  // tf32 relu(raw@W1+b1)
__device__ __align__(16) uint32_t g_x   [(size_t)B_EVT * KGRU];   // tf32 [msg|0|h|0]
__device__ __align__(16) float    g_h   [(size_t)B_EVT * H_P];    // fp32 h (epilogue)
__device__ __align__(16) uint32_t g_w1t [(size_t)RAW_P * W1_P];
__device__ __align__(16) uint32_t g_w2t [(size_t)ACT_P * W2_P];
__device__ __align__(16) uint32_t g_wstk[(size_t)KGRU * WSTK_P];

__device__ __forceinline__ float sigmoidf_(float x) { return 1.f / (1.f + expf(-x)); }
__device__ __forceinline__ uint32_t f2tf32(float x) {
    uint32_t r; asm("cvt.rna.tf32.f32 %0, %1;" : "=r"(r) : "f"(x)); return r;
}
__device__ __forceinline__ void mma8(float c[4], const uint32_t a[4], const uint32_t b[2]) {
    asm volatile(
        "mma.sync.aligned.m16n8k8.row.col.f32.tf32.tf32.f32 "
        "{%0,%1,%2,%3},{%4,%5,%6,%7},{%8,%9},{%0,%1,%2,%3};"
        : "+f"(c[0]), "+f"(c[1]), "+f"(c[2]), "+f"(c[3])
        : "r"(a[0]), "r"(a[1]), "r"(a[2]), "r"(a[3]), "r"(b[0]), "r"(b[1]));
}
__device__ __forceinline__ void cpa16(uint32_t dst, const void* src, int nbytes) {
    asm volatile("cp.async.cg.shared.global [%0], [%1], 16, %2;"
                 :: "r"(dst), "l"(src), "r"(nbytes));
}
#define CPA_COMMIT() asm volatile("cp.async.commit_group;")
#define CPA_WAIT1()  asm volatile("cp.async.wait_group 1;")

// ---------------- winner: last event index per node ----------------
__global__ void k_winner(const int* __restrict__ node_ids) {
    int e = blockIdx.x * blockDim.x + threadIdx.x;
    if (e < B_EVT) atomicMax(&g_winner[node_ids[e]], e);
}

// ---------------- weight packing (tf32, zero-padded) ----------------
__global__ void k_prep_w1(const float* __restrict__ W1) {
    int i = blockIdx.x * blockDim.x + threadIdx.x;
    if (i >= RAW_P * W1_P) return;
    int k = i / W1_P, n = i - k * W1_P;
    float v = (k < RAW_D && n < 350) ? W1[k * 350 + n] : 0.f;
    g_w1t[i] = f2tf32(v);
}
__global__ void k_prep_w2(const float* __restrict__ W2) {
    int i = blockIdx.x * blockDim.x + threadIdx.x;
    if (i >= ACT_P * W2_P) return;
    int k = i / W2_P, n = i - k * W2_P;
    float v = (k < 350 && n < MSG_D) ? W2[k * MSG_D + n] : 0.f;
    g_w2t[i] = f2tf32(v);
}
__global__ void k_prep_ws(const float* __restrict__ W_ih, const float* __restrict__ W_hh) {
    int i = blockIdx.x * blockDim.x + threadIdx.x;
    if (i >= KGRU * WSTK_P) return;
    int k = i / WSTK_P, n = i - k * WSTK_P;
    int g = n / SLAB, c = n - g * SLAB;
    float v = 0.f;
    if (c < MEM_D) {
        if (k < MSG_D)                      v = W_ih[k * 1500 + g * MEM_D + c];
        else if (k >= KB && k < KB + MEM_D) v = W_hh[(k - KB) * 1500 + g * MEM_D + c];
    }
    g_wstk[i] = f2tf32(v);
}

// ---------------- raw build (tf32 raw, tf32 x.h, fp32 h) ----------------
// cos arg is O(1e6): mul and add rounded SEPARATELY (matches XLA), accurate cosf.
__global__ void k_raw(const float* __restrict__ memory,
                      const float* __restrict__ last_update,
                      const float* __restrict__ edge_feats,
                      const float* __restrict__ w_t,
                      const float* __restrict__ b_t,
                      const int*   __restrict__ node_ids,
                      const int*   __restrict__ edge_times) {
    int e = blockIdx.x;
    int n = node_ids[e];
    float dt = __fadd_rn((float)edge_times[e], -last_update[n]);
    const float* mrow = memory + (size_t)n * MEM_D;
    uint32_t* rdst = g_rawt + (size_t)e * RAW_P;
    uint32_t* xdst = g_x    + (size_t)e * KGRU;
    float*    hdst = g_h    + (size_t)e * H_P;
    if (threadIdx.x < 4) {
        xdst[MSG_D + threadIdx.x] = 0u;          // x cols 100..104
        xdst[KB + MEM_D + threadIdx.x] = 0u;     // x cols 604..608
    }
    for (int i = threadIdx.x; i < RAW_P; i += blockDim.x) {
        float v;
        if (i < MEM_D) {
            v = mrow[i];
            hdst[i] = v;
            xdst[KB + i] = f2tf32(v);
        } else if (i < MEM_D + EDGE_F) {
            v = edge_feats[(size_t)e * EDGE_F + (i - MEM_D)];
        } else if (i < RAW_D) {
            int t = i - (MEM_D + EDGE_F);
            float arg = __fadd_rn(__fmul_rn(dt, w_t[t]), b_t[t]);
            v = cosf(arg);
        } else v = 0.f;
        rdst[i] = f2tf32(v);
    }
}

// ---------------- pipelined TF32 GEMM (3-stage cp.async) ----------------
// BM=128,BN=64,BK=32. 8 warps 4m x 2n, warp tile 32x32 (mf2 x nf4).
// A: tf32 [M x Kpad] (lda % 4 == 0). W: tf32, pitch ldw, rows >= Kpad, cols cover
// n-blocks exactly (prepacked, zero-padded). Output: tf32 into C (uint32), cols
// < nstore; bias added for col < nbias; optional ReLU.
#define AS_U32 4608          // 128*36
#define WS_U32 2304          // 32*72
#define STG_U32 (AS_U32 + WS_U32)
template<int RELU>
__global__ __launch_bounds__(256, 2)
void k_gemm_t(const uint32_t* __restrict__ A, int lda,
              const uint32_t* __restrict__ W, int ldw,
              const float* __restrict__ bias, int nbias,
              uint32_t* __restrict__ C, int ldc, int nstore,
              int Kpad) {
    extern __shared__ uint32_t sh[];
    const int tid = threadIdx.x;
    const int lane = tid & 31, wid = tid >> 5;
    const int gid = lane >> 2, tig = lane & 3;
    const int wm = wid >> 1, wn = wid & 1;
    const int n0 = blockIdx.x * 64, m0 = blockIdx.y * 128;
    const int KT = Kpad >> 5;
    const uint32_t shb = (uint32_t)__cvta_generic_to_shared(sh);

    // cp.async thread mapping
    const int am = (tid >> 1);                 // +64 per it (4 its): A row within tile
    const int ak = (tid & 1) * 16;             // two 16-float half-rows? no: chunk col
    // A: 1024 chunks: chunk c -> m=c>>3, kq=(c&7)*4 ; thread does c=tid,tid+256,...
    // W: 512 chunks: c -> k=c>>4, nq=(c&15)*4 ; thread does c=tid, tid+256
    (void)am; (void)ak;

    float acc[2][4][4];
#pragma unroll
    for (int i = 0; i < 2; i++)
#pragma unroll
        for (int j = 0; j < 4; j++)
#pragma unroll
            for (int c = 0; c < 4; c++) acc[i][j][c] = 0.f;

    auto issue = [&](int kt, int buf) {
        const int k0 = kt << 5;
        uint32_t abase = shb + (uint32_t)(buf * STG_U32) * 4u;
        uint32_t wbase = abase + AS_U32 * 4u;
#pragma unroll
        for (int it = 0; it < 4; it++) {
            int c = tid + it * 256;
            int m = c >> 3, kq = (c & 7) * 4;
            int gm = m0 + m;
            int ok = (gm < B_EVT) ? 16 : 0;
            int gmc = (gm < B_EVT) ? gm : 0;
            cpa16(abase + (uint32_t)(m * 36 + kq) * 4u,
                  A + (size_t)gmc * lda + k0 + kq, ok);
        }
#pragma unroll
        for (int it = 0; it < 2; it++) {
            int c = tid + it * 256;
            int k = c >> 4, nq = (c & 15) * 4;
            cpa16(wbase + (uint32_t)(k * 72 + nq) * 4u,
                  W + (size_t)(k0 + k) * ldw + n0 + nq, 16);
        }
    };

    issue(0, 0); CPA_COMMIT();
    issue(1, 1); CPA_COMMIT();

    for (int kt = 0; kt < KT; kt++) {
        CPA_WAIT1();
        __syncthreads();
        if (kt + 2 < KT) issue(kt + 2, (kt + 2) % 3);
        CPA_COMMIT();
        const uint32_t* As = sh + (kt % 3) * STG_U32;          // [128][36]
        const uint32_t* Ws = As + AS_U32;                       // [32][72]
#pragma unroll
        for (int s = 0; s < 4; s++) {
            int kb = s * 8;
            uint32_t a[2][4], b[4][2];
#pragma unroll
            for (int mf = 0; mf < 2; mf++) {
                int r0 = wm * 32 + mf * 16 + gid;
                a[mf][0] = As[(r0)     * 36 + kb + tig];
                a[mf][1] = As[(r0 + 8) * 36 + kb + tig];
                a[mf][2] = As[(r0)     * 36 + kb + tig + 4];
                a[mf][3] = As[(r0 + 8) * 36 + kb + tig + 4];
            }
#pragma unroll
            for (int nf = 0; nf < 4; nf++) {
                int c0 = wn * 32 + nf * 8 + gid;
                b[nf][0] = Ws[(kb + tig)     * 72 + c0];
                b[nf][1] = Ws[(kb + tig + 4) * 72 + c0];
            }
#pragma unroll
            for (int mf = 0; mf < 2; mf++)
#pragma unroll
                for (int nf = 0; nf < 4; nf++) mma8(acc[mf][nf], a[mf], b[nf]);
        }
        __syncthreads();
    }

#pragma unroll
    for (int mf = 0; mf < 2; mf++)
#pragma unroll
        for (int nf = 0; nf < 4; nf++)
#pragma unroll
            for (int c = 0; c < 4; c++) {
                int row = m0 + wm * 32 + mf * 16 + gid + ((c & 2) ? 8 : 0);
                int col = n0 + wn * 32 + nf * 8 + tig * 2 + (c & 1);
                if (row < B_EVT && col < nstore) {
                    float v = acc[mf][nf][c] + ((col < nbias) ? bias[col] : 0.f);
                    if (RELU) v = fmaxf(v, 0.f);
                    C[(size_t)row * ldc + col] = f2tf32(v);
                }
            }
}

// ---------------- pipelined fused TF32 GRU ----------------
// BM=128, BN=32 output cols, 3 gate slabs. 8 warps 4m x 2n, warp 32x16 (mf2 x nf2).
#define XS_U32 4608          // 128*36
#define WG_U32 1280          // 32*40 per gate
#define GSTG_U32 (XS_U32 + 3 * WG_U32)
__global__ __launch_bounds__(256, 2)
void k_gru_t(const float* __restrict__ b_ih,
             const float* __restrict__ b_hh,
             float* __restrict__ out) {
    extern __shared__ uint32_t sh[];
    const int tid = threadIdx.x;
    const int lane = tid & 31, wid = tid >> 5;
    const int gid = lane >> 2, tig = lane & 3;
    const int wm = wid >> 1, wn = wid & 1;
    const int n0 = blockIdx.x * 32, m0 = blockIdx.y * 128;
    const int KT = KGRU >> 5;   // 19
    const uint32_t shb = (uint32_t)__cvta_generic_to_shared(sh);

    float ar[2][2][4], az[2][2][4], ani[2][2][4], anh[2][2][4];
#pragma unroll
    for (int i = 0; i < 2; i++)
#pragma unroll
        for (int j = 0; j < 2; j++)
#pragma unroll
            for (int c = 0; c < 4; c++) {
                ar[i][j][c] = az[i][j][c] = ani[i][j][c] = anh[i][j][c] = 0.f;
            }

    auto issue = [&](int kt, int buf) {
        const int k0 = kt << 5;
        uint32_t xbase = shb + (uint32_t)(buf * GSTG_U32) * 4u;
        uint32_t wbase = xbase + XS_U32 * 4u;
#pragma unroll
        for (int it = 0; it < 4; it++) {
            int c = tid + it * 256;
            int m = c >> 3, kq = (c & 7) * 4;
            int gm = m0 + m;
            int ok = (gm < B_EVT) ? 16 : 0;
            int gmc = (gm < B_EVT) ? gm : 0;
            cpa16(xbase + (uint32_t)(m * 36 + kq) * 4u,
                  g_x + (size_t)gmc * KGRU + k0 + kq, ok);
        }
#pragma unroll
        for (int it = 0; it < 3; it++) {
            int c = tid + it * 256;
            int g = c >> 8, r = c & 255;
            int k = r >> 3, nq = (r & 7) * 4;
            cpa16(wbase + (uint32_t)(g * WG_U32 + k * 40 + nq) * 4u,
                  g_wstk + (size_t)(k0 + k) * WSTK_P + g * SLAB + n0 + nq, 16);
        }
    };

    issue(0, 0); CPA_COMMIT();
    issue(1, 1); CPA_COMMIT();

    for (int kt = 0; kt < KT; kt++) {
        CPA_WAIT1();
        __syncthreads();
        if (kt + 2 < KT) issue(kt + 2, (kt + 2) % 3);
        CPA_COMMIT();
        const uint32_t* Xs = sh + (kt % 3) * GSTG_U32;          // [128][36]
        const uint32_t* Wg = Xs + XS_U32;                        // [3][32][40]
        const int k0 = kt << 5;
#pragma unroll
        for (int s = 0; s < 4; s++) {
            int kb = s * 8;
            bool ihSide = (k0 + kb) < KB;
            uint32_t a[2][4], br[2][2], bz[2][2], bn[2][2];
#pragma unroll
            for (int mf = 0; mf < 2; mf++) {
                int r0 = wm * 32 + mf * 16 + gid;
                a[mf][0] = Xs[(r0)     * 36 + kb + tig];
                a[mf][1] = Xs[(r0 + 8) * 36 + kb + tig];
                a[mf][2] = Xs[(r0)     * 36 + kb + tig + 4];
                a[mf][3] = Xs[(r0 + 8) * 36 + kb + tig + 4];
            }
#pragma unroll
            for (int nf = 0; nf < 2; nf++) {
                int c0 = wn * 16 + nf * 8 + gid;
                br[nf][0] = Wg[0 * WG_U32 + (kb + tig)     * 40 + c0];
                br[nf][1] = Wg[0 * WG_U32 + (kb + tig + 4) * 40 + c0];
                bz[nf][0] = Wg[1 * WG_U32 + (kb + tig)     * 40 + c0];
                bz[nf][1] = Wg[1 * WG_U32 + (kb + tig + 4) * 40 + c0];
                bn[nf][0] = Wg[2 * WG_U32 + (kb + tig)     * 40 + c0];
                bn[nf][1] = Wg[2 * WG_U32 + (kb + tig + 4) * 40 + c0];
            }
#pragma unroll
            for (int mf = 0; mf < 2; mf++)
#pragma unroll
                for (int nf = 0; nf < 2; nf++) {
                    mma8(ar[mf][nf], a[mf], br[nf]);
                    mma8(az[mf][nf], a[mf], bz[nf]);
                    if (ihSide) mma8(ani[mf][nf], a[mf], bn[nf]);
                    else        mma8(anh[mf][nf], a[mf], bn[nf]);
                }
        }
        __syncthreads();
    }

#pragma unroll
    for (int mf = 0; mf < 2; mf++)
#pragma unroll
        for (int nf = 0; nf < 2; nf++)
#pragma unroll
            for (int c = 0; c < 4; c++) {
                int rm = m0 + wm * 32 + mf * 16 + gid + ((c & 2) ? 8 : 0);
                int cn = n0 + wn * 16 + nf * 8 + tig * 2 + (c & 1);
                if (rm < B_EVT && cn < MEM_D) {
                    float r  = sigmoidf_(ar[mf][nf][c] + b_ih[cn] + b_hh[cn]);
                    float z  = sigmoidf_(az[mf][nf][c] + b_ih[MEM_D + cn] + b_hh[MEM_D + cn]);
                    float nn = tanhf(ani[mf][nf][c] + b_ih[2 * MEM_D + cn] +
                                     r * (anh[mf][nf][c] + b_hh[2 * MEM_D + cn]));
                    float h  = g_h[(size_t)rm * H_P + cn];
                    out[(size_t)rm * MEM_D + cn] = (1.f - z) * nn + z * h;
                }
            }
}

// ---------------- non-winner rows copy the winner's row ----------------
__global__ void k_fixup(const int* __restrict__ node_ids, float* __restrict__ out) {
    int e = blockIdx.x;
    int w = g_winner[node_ids[e]];
    if (w == e) return;
    const float4* src = (const float4*)(out + (size_t)w * MEM_D);
    float4*       dst = (float4*)(out + (size_t)e * MEM_D);
    for (int i = threadIdx.x; i < MEM_D / 4; i += blockDim.x) dst[i] = src[i];
}

// ---------------- launch ----------------
extern "C" void kernel_launch(void* const* d_in, const int* in_sizes, int n_in,
                              void* d_out, int out_size) {
    const float* memory      = (const float*)d_in[0];
    const float* last_update = (const float*)d_in[1];
    const float* edge_feats  = (const float*)d_in[2];
    const float* w_t         = (const float*)d_in[3];
    const float* b_t         = (const float*)d_in[4];
    const float* W1          = (const float*)d_in[5];
    const float* b1          = (const float*)d_in[6];
    const float* W2          = (const float*)d_in[7];
    const float* b2          = (const float*)d_in[8];
    const float* W_ih        = (const float*)d_in[9];
    const float* W_hh        = (const float*)d_in[10];
    const float* b_ih        = (const float*)d_in[11];
    const float* b_hh        = (const float*)d_in[12];
    // d_in[13] default_memory: dead (all output nodes touched, times >= 1)
    const int*   node_ids    = (const int*)d_in[14];
    const int*   edge_times  = (const int*)d_in[15];
    float* out = (float*)d_out;

    static int attr_done = 0;
    const int SM_GEMM = STG_U32 * 3 * 4;   // 82944 B
    const int SM_GRU  = GSTG_U32 * 3 * 4;  // 101376 B
    if (!attr_done) {
        cudaFuncSetAttribute(k_gemm_t<1>, cudaFuncAttributeMaxDynamicSharedMemorySize, SM_GEMM);
        cudaFuncSetAttribute(k_gemm_t<0>, cudaFuncAttributeMaxDynamicSharedMemorySize, SM_GEMM);
        cudaFuncSetAttribute(k_gru_t,     cudaFuncAttributeMaxDynamicSharedMemorySize, SM_GRU);
        attr_done = 1;
    }

    void *winner_p, *rawt_p, *act_p, *x_p, *w1_p, *w2_p, *ws_p;
    cudaGetSymbolAddress(&winner_p, g_winner);
    cudaGetSymbolAddress(&rawt_p,   g_rawt);
    cudaGetSymbolAddress(&act_p,    g_act);
    cudaGetSymbolAddress(&x_p,      g_x);
    cudaGetSymbolAddress(&w1_p,     g_w1t);
    cudaGetSymbolAddress(&w2_p,     g_w2t);
    cudaGetSymbolAddress(&ws_p,     g_wstk);

    cudaMemsetAsync(winner_p, 0xFF, sizeof(int) * N_NODES);
    k_winner<<<(B_EVT + 255) / 256, 256>>>(node_ids);
    k_prep_w1<<<(RAW_P * W1_P + 255) / 256, 256>>>(W1);
    k_prep_w2<<<(ACT_P * W2_P + 255) / 256, 256>>>(W2);
    k_prep_ws<<<(KGRU * WSTK_P + 255) / 256, 256>>>(W_ih, W_hh);
    k_raw<<<B_EVT, 128>>>(memory, last_update, edge_feats, w_t, b_t, node_ids, edge_times);

    // MLP1: act(tf32) = relu(raw @ W1 + b1); 6 n-blocks cover 384 >= 352
    {
        dim3 g(6, MBLK);
        k_gemm_t<1><<<g, 256, SM_GEMM>>>((const uint32_t*)rawt_p, RAW_P,
                                         (const uint32_t*)w1_p, W1_P,
                                         b1, 350,
                                         (uint32_t*)act_p, ACT_P, ACT_P, RAW_P);
    }
    // MLP2: msg(tf32) -> g_x cols [0,100)
    {
        dim3 g(2, MBLK);
        k_gemm_t<0><<<g, 256, SM_GEMM>>>((const uint32_t*)act_p, ACT_P,
                                         (const uint32_t*)w2_p, W2_P,
                                         b2, MSG_D,
                                         (uint32_t*)x_p, KGRU, MSG_D, ACT_P);
    }
    // Fused GRU -> out
    {
        dim3 g(16, MBLK);
        k_gru_t<<<g, 256, SM_GRU>>>(b_ih, b_hh, out);
    }
    k_fixup<<<B_EVT, 128>>>(node_ids, out);
}